// round 4
// baseline (speedup 1.0000x reference)
#include <cuda_runtime.h>

#define BNN 16384   // 16*32*32

// ---------------- scratch (device globals) ----------------------------------
__device__ float g_Koa[512*128];
__device__ float g_Qoa[512*128];
__device__ float g_Voa[512*128];
__device__ float g_Vop[512*128];
__device__ float g_Ko [512*128];
__device__ float g_Qo [512*128];
__device__ float g_AVO[512*128];
__device__ float g_A  [512*64];
__device__ float g_C  [512*64];
__device__ float g_woa[512*32];
__device__ float g_M  [16384*128];   // per-(b,k,j) noise i-sum, 8MB (L2-resident)

__device__ __forceinline__ float dot4(float4 a, float4 b){
    return a.x*b.x + a.y*b.y + a.z*b.z + a.w*b.w;
}

// ---------------- kernel 1: the 7 linear projections ------------------------
__global__ __launch_bounds__(256) void proj_kernel(
    const float* __restrict__ states, const float* __restrict__ policies,
    const float* __restrict__ actions,
    const float* __restrict__ Wk_oa, const float* __restrict__ Wq_oa,
    const float* __restrict__ Wv_oa, const float* __restrict__ Wk_o,
    const float* __restrict__ Wq_o,  const float* __restrict__ Wv_o)
{
    __shared__ float IN [32*148];
    __shared__ float Wsm[32*148];
    int b = blockIdx.x, m = blockIdx.y, dz = blockIdx.z;
    int tid = threadIdx.x;
    int E = (m < 4) ? 144 : 128;
    const float* W = (m==0)?Wk_oa:(m==1)?Wq_oa:(m<=3)?Wv_oa:(m==4)?Wk_o:(m==5)?Wq_o:Wv_o;
    float* OUT = (m==0)?g_Koa:(m==1)?g_Qoa:(m==2)?g_Voa:(m==3)?g_Vop:(m==4)?g_Ko:(m==5)?g_Qo:g_AVO;

    for (int idx = tid; idx < 32*E; idx += 256) {
        int a = idx / E, e = idx - a*E;
        float v;
        if (e < 128) v = states[(b*32+a)*128 + e];
        else {
            int c = e - 128;
            v = (m == 3) ? policies[(b*32+a)*16 + c] : actions[(b*32+a)*16 + c];
        }
        IN[a*148 + e] = v;
    }
    for (int idx = tid; idx < 32*E; idx += 256) {
        int r = idx / E, e = idx - r*E;
        Wsm[r*148 + e] = W[(dz*32+r)*E + e];
    }
    __syncthreads();

    int r = tid & 31, g = tid >> 5;
    float acc0=0.f, acc1=0.f, acc2=0.f, acc3=0.f;
    const float4* wr = (const float4*)(Wsm + r*148);
    const float4* x0 = (const float4*)(IN + (g*4+0)*148);
    const float4* x1 = (const float4*)(IN + (g*4+1)*148);
    const float4* x2 = (const float4*)(IN + (g*4+2)*148);
    const float4* x3 = (const float4*)(IN + (g*4+3)*148);
    int nch = E >> 2;
    #pragma unroll 4
    for (int e4 = 0; e4 < nch; e4++) {
        float4 w = wr[e4];
        acc0 += dot4(w, x0[e4]);
        acc1 += dot4(w, x1[e4]);
        acc2 += dot4(w, x2[e4]);
        acc3 += dot4(w, x3[e4]);
    }
    int dg = dz*32 + r;
    OUT[(b*32 + g*4+0)*128 + dg] = acc0;
    OUT[(b*32 + g*4+1)*128 + dg] = acc1;
    OUT[(b*32 + g*4+2)*128 + dg] = acc2;
    OUT[(b*32 + g*4+3)*128 + dg] = acc3;
}

// ---------------- kernel 2: pure noise streaming reduction -------------------
// warp per (b,k,j) tile: sum 32 i-rows of 128 floats. No smem, no syncs.
__global__ __launch_bounds__(256) void reduce_kernel(const float4* __restrict__ np)
{
    int t = blockIdx.x*256 + threadIdx.x;
    int tile = t >> 5, lane = t & 31;
    const float4* p = np + (tile << 10) + lane;
    float4 acc = make_float4(0.f,0.f,0.f,0.f);
    #pragma unroll
    for (int i = 0; i < 32; i++) {
        float4 v = __ldcs(p + (i << 5));
        acc.x += v.x; acc.y += v.y; acc.z += v.z; acc.w += v.w;
    }
    ((float4*)g_M)[(tile << 5) + lane] = acc;
}

// ---------------- kernel 3: fused attention (both branches) + A/C fold -------
// grid (16 b, 4 agent-octet), 256 threads.
__global__ __launch_bounds__(256) void attac_kernel(
    const float* __restrict__ W1, float* __restrict__ out)
{
    __shared__ float sbig[8320];   // att: sQ(32*132=4224)+sV(32*128=4096); ac: W^T (128*65)
    __shared__ float sK[8*128];    // att K rows; later wfo rows
    __shared__ float sS[8*128];    // raw S (obs-action weighted value sum)
    __shared__ float sD[8*128];    // (Vop-Voa)/32
    float* sQ  = sbig;
    float* sV  = sbig + 4224;
    float* sWT = sbig;

    int b = blockIdx.x, q = blockIdx.y, tid = threadIdx.x;
    int kk = tid >> 5, i = tid & 31, k = q*8 + kk;

    for (int p = 0; p < 2; p++) {
        const float* Qp = p ? g_Qo  : g_Qoa;
        const float* Kp = p ? g_Ko  : g_Koa;
        const float* Vp = p ? g_AVO : g_Voa;
        if (p) __syncthreads();
        const float4* Q4 = (const float4*)(Qp + b*32*128);
        const float4* V4 = (const float4*)(Vp + b*32*128);
        for (int idx = tid; idx < 1024; idx += 256) {
            int a = idx >> 5, e4 = idx & 31;
            *(float4*)(sQ + a*132 + e4*4) = Q4[idx];
            ((float4*)sV)[idx] = V4[idx];
        }
        const float4* K4 = (const float4*)(Kp + (b*32 + q*8)*128);
        if (tid < 256) ((float4*)sK)[tid] = K4[tid];
        __syncthreads();

        const float4* qr = (const float4*)(sQ + i*132);
        const float4* kr = (const float4*)(sK + kk*128);
        float acc = 0.f;
        #pragma unroll
        for (int e4 = 0; e4 < 32; e4++) acc += dot4(qr[e4], kr[e4]);
        float v = acc * 0.08838834764831845f;   // 1/sqrt(128)
        float mx = v;
        #pragma unroll
        for (int off = 16; off; off >>= 1) mx = fmaxf(mx, __shfl_xor_sync(0xffffffffu, mx, off));
        float ex = __expf(v - mx);
        float sm = ex;
        #pragma unroll
        for (int off = 16; off; off >>= 1) sm += __shfl_xor_sync(0xffffffffu, sm, off);
        float w = ex / sm;
        out[(p ? 2*BNN : BNN) + (b*32+k)*32 + i] = w;
        if (!p) g_woa[(b*32+k)*32 + i] = w;
        if (p) __syncthreads();   // all score reads of sK done before wfo overwrites it

        float4 a4 = make_float4(0.f,0.f,0.f,0.f);
        #pragma unroll
        for (int i2 = 0; i2 < 32; i2++) {
            float wv = __shfl_sync(0xffffffffu, w, i2);
            float4 vv = ((const float4*)sV)[i2*32 + i];
            a4.x += wv*vv.x; a4.y += wv*vv.y; a4.z += wv*vv.z; a4.w += wv*vv.w;
        }
        if (!p) {
            ((float4*)sS)[kk*32 + i] = a4;
        } else {
            float4 sc = make_float4(a4.x*0.03125f, a4.y*0.03125f, a4.z*0.03125f, a4.w*0.03125f);
            ((float4*)sK)[kk*32 + i] = sc;    // wfo
        }
    }
    __syncthreads();   // sV reads done -> safe to overlay sWT; wfo/sS complete

    {
        int base = (b*32 + q*8)*128;
        for (int idx = tid; idx < 1024; idx += 256)
            sD[idx] = (g_Vop[base+idx] - g_Voa[base+idx]) * 0.03125f;
        for (int idx = tid; idx < 8192; idx += 256) {   // W1a^T (coalesced load)
            int hh = idx >> 7, e = idx & 127;
            sWT[e*65 + hh] = W1[hh*256 + e];
        }
    }
    __syncthreads();

    int h = tid & 63, grp = tid >> 6;    // 2 agents per grp
    const float* wf0 = sK + (grp*2  )*128;
    const float* wf1 = sK + (grp*2+1)*128;
    float accA0 = 0.f, accA1 = 0.f;
    #pragma unroll 4
    for (int e = 0; e < 128; e++) {
        float w = sWT[e*65 + h];
        accA0 += w*wf0[e]; accA1 += w*wf1[e];
    }
    __syncthreads();
    for (int idx = tid; idx < 8192; idx += 256) {       // W1b^T
        int hh = idx >> 7, e = idx & 127;
        sWT[e*65 + hh] = W1[hh*256 + 128 + e];
    }
    __syncthreads();

    const float* s0 = sS + grp*2*128; const float* s1 = s0 + 128;
    const float* d0 = sD + grp*2*128; const float* d1 = d0 + 128;
    float aS0=0.f, aS1=0.f, aD0=0.f, aD1=0.f, aW=0.f;
    #pragma unroll 4
    for (int e = 0; e < 128; e++) {
        float w = sWT[e*65 + h];
        aW  += w;
        aS0 += w*s0[e]; aS1 += w*s1[e];
        aD0 += w*d0[e]; aD1 += w*d1[e];
    }
    int ga = b*32 + q*8 + grp*2;
    g_A[ ga   *64 + h] = accA0 + 0.03125f*aS0 - 0.05f*aW;
    g_A[(ga+1)*64 + h] = accA1 + 0.03125f*aS1 - 0.05f*aW;
    g_C[ ga   *64 + h] = aD0;
    g_C[(ga+1)*64 + h] = aD1;
}

// ---------------- kernel 4: H = M @ W1b^T + epilogue -> value ----------------
// 128 blocks x 256 threads; block computes 128 rows x 64 h with 8x4 reg tiles.
__global__ __launch_bounds__(256) void gemm_kernel(
    const float* __restrict__ W1, const float* __restrict__ W2,
    float* __restrict__ out)
{
    __shared__ float Ms[128*36];    // 128 rows x 32-k chunk, pad 36
    __shared__ float Ws[32*68];     // W1b^T chunk [k][h], pad 68
    int R0 = blockIdx.x * 128;
    int tid = threadIdx.x;
    int tx = tid & 15, ty = tid >> 4;   // tx -> h quad, ty -> 8-row group

    float4 acc[8];
    #pragma unroll
    for (int qq = 0; qq < 8; qq++) acc[qq] = make_float4(0.f,0.f,0.f,0.f);

    for (int kc = 0; kc < 4; kc++) {
        __syncthreads();
        for (int idx = tid; idx < 1024; idx += 256) {
            int r = idx >> 3, c4 = idx & 7;
            *(float4*)(Ms + r*36 + c4*4) = ((const float4*)g_M)[(R0+r)*32 + kc*8 + c4];
        }
        for (int idx = tid; idx < 2048; idx += 256) {
            int hh = idx >> 5, k2 = idx & 31;
            Ws[k2*68 + hh] = W1[hh*256 + 128 + kc*32 + k2];
        }
        __syncthreads();
        #pragma unroll
        for (int k2 = 0; k2 < 32; k2++) {
            float4 w = *(const float4*)(Ws + k2*68 + tx*4);
            #pragma unroll
            for (int qq = 0; qq < 8; qq++) {
                float m = Ms[(ty*8+qq)*36 + k2];
                acc[qq].x += m*w.x; acc[qq].y += m*w.y;
                acc[qq].z += m*w.z; acc[qq].w += m*w.w;
            }
        }
    }

    float4 w2 = *(const float4*)(W2 + tx*4);
    #pragma unroll
    for (int qq = 0; qq < 8; qq++) {
        int row = R0 + ty*8 + qq;
        int bk = row >> 5, j = row & 31, b = row >> 10;
        float4 a4 = *(const float4*)(g_A + bk*64 + tx*4);
        float4 c4 = *(const float4*)(g_C + ((b<<5)+j)*64 + tx*4);
        float wo = g_woa[row];
        float px = a4.x + wo*c4.x + 0.003125f*acc[qq].x;
        float py = a4.y + wo*c4.y + 0.003125f*acc[qq].y;
        float pz = a4.z + wo*c4.z + 0.003125f*acc[qq].z;
        float pw = a4.w + wo*c4.w + 0.003125f*acc[qq].w;
        px = px > 0.f ? px : 0.01f*px;
        py = py > 0.f ? py : 0.01f*py;
        pz = pz > 0.f ? pz : 0.01f*pz;
        pw = pw > 0.f ? pw : 0.01f*pw;
        float val = px*w2.x + py*w2.y + pz*w2.z + pw*w2.w;
        #pragma unroll
        for (int off = 8; off; off >>= 1) val += __shfl_down_sync(0xffffffffu, val, off);
        if (tx == 0) out[row] = val;
    }
}

// ---------------- launch: fork noise reduction onto a side stream ------------
extern "C" void kernel_launch(void* const* d_in, const int* in_sizes, int n_in,
                              void* d_out, int out_size)
{
    const float* states   = (const float*)d_in[0];
    const float* policies = (const float*)d_in[1];
    const float* actions  = (const float*)d_in[2];
    const float* noise    = (const float*)d_in[3];
    const float* Wk_oa    = (const float*)d_in[4];
    const float* Wq_oa    = (const float*)d_in[5];
    const float* Wv_oa    = (const float*)d_in[6];
    const float* Wk_o     = (const float*)d_in[7];
    const float* Wq_o     = (const float*)d_in[8];
    const float* Wv_o     = (const float*)d_in[9];
    const float* W1       = (const float*)d_in[10];
    const float* W2       = (const float*)d_in[11];
    float* out = (float*)d_out;

    static cudaStream_t s2 = nullptr;
    static cudaEvent_t evA = nullptr, evB = nullptr;
    if (!s2) {
        cudaStreamCreateWithFlags(&s2, cudaStreamNonBlocking);
        cudaEventCreateWithFlags(&evA, cudaEventDisableTiming);
        cudaEventCreateWithFlags(&evB, cudaEventDisableTiming);
    }

    // fork: noise reduction runs concurrently with proj+attac
    cudaEventRecord(evA, 0);
    cudaStreamWaitEvent(s2, evA, 0);
    reduce_kernel<<<2048, 256, 0, s2>>>((const float4*)noise);
    cudaEventRecord(evB, s2);

    proj_kernel<<<dim3(16,7,4), 256>>>(states, policies, actions,
                                       Wk_oa, Wq_oa, Wv_oa, Wk_o, Wq_o, Wv_o);
    attac_kernel<<<dim3(16,4), 256>>>(W1, out);

    cudaStreamWaitEvent(0, evB, 0);
    gemm_kernel<<<128, 256>>>(W1, W2, out);
}

// round 5
// speedup vs baseline: 1.0928x; 1.0928x over previous
#include <cuda_runtime.h>

#define BNN 16384   // 16*32*32

// ---------------- scratch (device globals) ----------------------------------
__device__ float g_Koa[512*128];
__device__ float g_Qoa[512*128];
__device__ float g_Voa[512*128];
__device__ float g_Vop[512*128];
__device__ float g_Ko [512*128];
__device__ float g_Qo [512*128];
__device__ float g_AVO[512*128];
__device__ float g_A  [512*64];
__device__ float g_C  [512*64];
__device__ float g_woa[512*32];

__device__ __forceinline__ float dot4(float4 a, float4 b){
    return a.x*b.x + a.y*b.y + a.z*b.z + a.w*b.w;
}

// ---------------- kernel 1: the 7 linear projections ------------------------
__global__ __launch_bounds__(256) void proj_kernel(
    const float* __restrict__ states, const float* __restrict__ policies,
    const float* __restrict__ actions,
    const float* __restrict__ Wk_oa, const float* __restrict__ Wq_oa,
    const float* __restrict__ Wv_oa, const float* __restrict__ Wk_o,
    const float* __restrict__ Wq_o,  const float* __restrict__ Wv_o)
{
    __shared__ float IN [32*148];
    __shared__ float Wsm[32*148];
    int b = blockIdx.x, m = blockIdx.y, dz = blockIdx.z;
    int tid = threadIdx.x;
    int E = (m < 4) ? 144 : 128;
    const float* W = (m==0)?Wk_oa:(m==1)?Wq_oa:(m<=3)?Wv_oa:(m==4)?Wk_o:(m==5)?Wq_o:Wv_o;
    float* OUT = (m==0)?g_Koa:(m==1)?g_Qoa:(m==2)?g_Voa:(m==3)?g_Vop:(m==4)?g_Ko:(m==5)?g_Qo:g_AVO;

    for (int idx = tid; idx < 32*E; idx += 256) {
        int a = idx / E, e = idx - a*E;
        float v;
        if (e < 128) v = states[(b*32+a)*128 + e];
        else {
            int c = e - 128;
            v = (m == 3) ? policies[(b*32+a)*16 + c] : actions[(b*32+a)*16 + c];
        }
        IN[a*148 + e] = v;
    }
    for (int idx = tid; idx < 32*E; idx += 256) {
        int r = idx / E, e = idx - r*E;
        Wsm[r*148 + e] = W[(dz*32+r)*E + e];
    }
    __syncthreads();

    int r = tid & 31, g = tid >> 5;
    float acc0=0.f, acc1=0.f, acc2=0.f, acc3=0.f;
    const float4* wr = (const float4*)(Wsm + r*148);
    const float4* x0 = (const float4*)(IN + (g*4+0)*148);
    const float4* x1 = (const float4*)(IN + (g*4+1)*148);
    const float4* x2 = (const float4*)(IN + (g*4+2)*148);
    const float4* x3 = (const float4*)(IN + (g*4+3)*148);
    int nch = E >> 2;
    #pragma unroll 4
    for (int e4 = 0; e4 < nch; e4++) {
        float4 w = wr[e4];
        acc0 += dot4(w, x0[e4]);
        acc1 += dot4(w, x1[e4]);
        acc2 += dot4(w, x2[e4]);
        acc3 += dot4(w, x3[e4]);
    }
    int dg = dz*32 + r;
    OUT[(b*32 + g*4+0)*128 + dg] = acc0;
    OUT[(b*32 + g*4+1)*128 + dg] = acc1;
    OUT[(b*32 + g*4+2)*128 + dg] = acc2;
    OUT[(b*32 + g*4+3)*128 + dg] = acc3;
}

// ---------------- kernel 2: fused attention (both branches) + A/C fold -------
__global__ __launch_bounds__(256) void attac_kernel(
    const float* __restrict__ W1, float* __restrict__ out)
{
    __shared__ float sbig[8320];   // att: sQ+sV; ac: W^T (128*65)
    __shared__ float sK[8*128];    // att K rows; later wfo rows
    __shared__ float sS[8*128];    // raw S
    __shared__ float sD[8*128];    // (Vop-Voa)/32
    float* sQ  = sbig;
    float* sV  = sbig + 4224;
    float* sWT = sbig;

    int b = blockIdx.x, q = blockIdx.y, tid = threadIdx.x;
    int kk = tid >> 5, i = tid & 31, k = q*8 + kk;

    for (int p = 0; p < 2; p++) {
        const float* Qp = p ? g_Qo  : g_Qoa;
        const float* Kp = p ? g_Ko  : g_Koa;
        const float* Vp = p ? g_AVO : g_Voa;
        if (p) __syncthreads();
        const float4* Q4 = (const float4*)(Qp + b*32*128);
        const float4* V4 = (const float4*)(Vp + b*32*128);
        for (int idx = tid; idx < 1024; idx += 256) {
            int a = idx >> 5, e4 = idx & 31;
            *(float4*)(sQ + a*132 + e4*4) = Q4[idx];
            ((float4*)sV)[idx] = V4[idx];
        }
        const float4* K4 = (const float4*)(Kp + (b*32 + q*8)*128);
        if (tid < 256) ((float4*)sK)[tid] = K4[tid];
        __syncthreads();

        const float4* qr = (const float4*)(sQ + i*132);
        const float4* kr = (const float4*)(sK + kk*128);
        float acc = 0.f;
        #pragma unroll
        for (int e4 = 0; e4 < 32; e4++) acc += dot4(qr[e4], kr[e4]);
        float v = acc * 0.08838834764831845f;   // 1/sqrt(128)
        float mx = v;
        #pragma unroll
        for (int off = 16; off; off >>= 1) mx = fmaxf(mx, __shfl_xor_sync(0xffffffffu, mx, off));
        float ex = __expf(v - mx);
        float sm = ex;
        #pragma unroll
        for (int off = 16; off; off >>= 1) sm += __shfl_xor_sync(0xffffffffu, sm, off);
        float w = ex / sm;
        out[(p ? 2*BNN : BNN) + (b*32+k)*32 + i] = w;
        if (!p) g_woa[(b*32+k)*32 + i] = w;
        if (p) __syncthreads();

        float4 a4 = make_float4(0.f,0.f,0.f,0.f);
        #pragma unroll
        for (int i2 = 0; i2 < 32; i2++) {
            float wv = __shfl_sync(0xffffffffu, w, i2);
            float4 vv = ((const float4*)sV)[i2*32 + i];
            a4.x += wv*vv.x; a4.y += wv*vv.y; a4.z += wv*vv.z; a4.w += wv*vv.w;
        }
        if (!p) {
            ((float4*)sS)[kk*32 + i] = a4;
        } else {
            float4 sc = make_float4(a4.x*0.03125f, a4.y*0.03125f, a4.z*0.03125f, a4.w*0.03125f);
            ((float4*)sK)[kk*32 + i] = sc;    // wfo
        }
    }
    __syncthreads();

    {
        int base = (b*32 + q*8)*128;
        for (int idx = tid; idx < 1024; idx += 256)
            sD[idx] = (g_Vop[base+idx] - g_Voa[base+idx]) * 0.03125f;
        for (int idx = tid; idx < 8192; idx += 256) {   // W1a^T
            int hh = idx >> 7, e = idx & 127;
            sWT[e*65 + hh] = W1[hh*256 + e];
        }
    }
    __syncthreads();

    int h = tid & 63, grp = tid >> 6;
    const float* wf0 = sK + (grp*2  )*128;
    const float* wf1 = sK + (grp*2+1)*128;
    float accA0 = 0.f, accA1 = 0.f;
    #pragma unroll 4
    for (int e = 0; e < 128; e++) {
        float w = sWT[e*65 + h];
        accA0 += w*wf0[e]; accA1 += w*wf1[e];
    }
    __syncthreads();
    for (int idx = tid; idx < 8192; idx += 256) {       // W1b^T
        int hh = idx >> 7, e = idx & 127;
        sWT[e*65 + hh] = W1[hh*256 + 128 + e];
    }
    __syncthreads();

    const float* s0 = sS + grp*2*128; const float* s1 = s0 + 128;
    const float* d0 = sD + grp*2*128; const float* d1 = d0 + 128;
    float aS0=0.f, aS1=0.f, aD0=0.f, aD1=0.f, aW=0.f;
    #pragma unroll 4
    for (int e = 0; e < 128; e++) {
        float w = sWT[e*65 + h];
        aW  += w;
        aS0 += w*s0[e]; aS1 += w*s1[e];
        aD0 += w*d0[e]; aD1 += w*d1[e];
    }
    int ga = b*32 + q*8 + grp*2;
    g_A[ ga   *64 + h] = accA0 + 0.03125f*aS0 - 0.05f*aW;
    g_A[(ga+1)*64 + h] = accA1 + 0.03125f*aS1 - 0.05f*aW;
    g_C[ ga   *64 + h] = aD0;
    g_C[(ga+1)*64 + h] = aD1;
}

// ---------------- kernel 3: fused noise stream + GEMV + epilogue -> value ----
// 1024 blocks x 512 threads. Warp per (b,k,j) tile (16 tiles/block, same (b,k)).
// Stream 16KB of noise, i-reduce in regs, GEMV vs W1b^T in smem, leaky+W2.
__global__ __launch_bounds__(512) void fused_kernel(
    const float4* __restrict__ np, const float* __restrict__ W1,
    const float* __restrict__ W2, float* __restrict__ out)
{
    __shared__ float WT [128*66];    // W1b^T [d][h], pad 66 (33.8 KB)
    __shared__ float Msm[16*132];    // per-warp i-sum rows (8.4 KB)
    __shared__ float Asm[64];
    __shared__ float woas[16];

    int blk = blockIdx.x;
    int tid = threadIdx.x;
    int w = tid >> 5, lane = tid & 31;
    int tile0 = blk * 16;            // b*1024 + k*32 + j0
    int bk = tile0 >> 5;             // b*32 + k
    int j0 = tile0 & 31;
    int b  = tile0 >> 10;

    // cooperative fills (independent of the noise stream)
    for (int idx = tid; idx < 8192; idx += 512) {
        int d = idx & 127, h = idx >> 7;        // coalesced read of W1 rows
        WT[d*66 + h] = W1[h*256 + 128 + d];
    }
    if (tid < 64) Asm[tid] = g_A[bk*64 + tid];
    if (tid < 16) woas[tid] = g_woa[bk*32 + j0 + tid];

    // noise i-reduction: warp w owns tile0+w; lane covers d[4l..4l+3]
    const float4* p = np + ((long)(tile0 + w) << 10) + lane;
    float4 acc = make_float4(0.f,0.f,0.f,0.f);
    #pragma unroll
    for (int i = 0; i < 32; i++) {
        float4 v = __ldcs(p + (i << 5));
        acc.x += v.x; acc.y += v.y; acc.z += v.z; acc.w += v.w;
    }
    *(float4*)(Msm + w*132 + lane*4) = acc;
    __syncthreads();

    // GEMV: lane computes h0=2*lane, h1=2*lane+1
    const float* mr = Msm + w*132;
    const float* wtl = WT + 2*lane;
    float a0 = 0.f, a1 = 0.f;
    #pragma unroll 4
    for (int d = 0; d < 128; d++) {
        float m = mr[d];                         // broadcast
        float2 wv = *(const float2*)(wtl + d*66); // conflict-free
        a0 += m*wv.x; a1 += m*wv.y;
    }

    // epilogue
    int j = j0 + w;
    float wo = woas[w];
    float2 c2 = *(const float2*)(g_C + (b*32 + j)*64 + 2*lane);
    float2 A2 = *(const float2*)(Asm + 2*lane);
    float p0 = A2.x + wo*c2.x + 0.003125f*a0;
    float p1 = A2.y + wo*c2.y + 0.003125f*a1;
    p0 = p0 > 0.f ? p0 : 0.01f*p0;
    p1 = p1 > 0.f ? p1 : 0.01f*p1;
    float val = p0*__ldg(W2 + 2*lane) + p1*__ldg(W2 + 2*lane + 1);
    #pragma unroll
    for (int off = 16; off; off >>= 1) val += __shfl_down_sync(0xffffffffu, val, off);
    if (lane == 0) out[tile0 + w] = val;
}

// ---------------- launch -----------------------------------------------------
extern "C" void kernel_launch(void* const* d_in, const int* in_sizes, int n_in,
                              void* d_out, int out_size)
{
    const float* states   = (const float*)d_in[0];
    const float* policies = (const float*)d_in[1];
    const float* actions  = (const float*)d_in[2];
    const float* noise    = (const float*)d_in[3];
    const float* Wk_oa    = (const float*)d_in[4];
    const float* Wq_oa    = (const float*)d_in[5];
    const float* Wv_oa    = (const float*)d_in[6];
    const float* Wk_o     = (const float*)d_in[7];
    const float* Wq_o     = (const float*)d_in[8];
    const float* Wv_o     = (const float*)d_in[9];
    const float* W1       = (const float*)d_in[10];
    const float* W2       = (const float*)d_in[11];
    float* out = (float*)d_out;

    proj_kernel<<<dim3(16,7,4), 256>>>(states, policies, actions,
                                       Wk_oa, Wq_oa, Wv_oa, Wk_o, Wq_o, Wv_o);
    attac_kernel<<<dim3(16,4), 256>>>(W1, out);
    fused_kernel<<<1024, 512>>>((const float4*)noise, W1, W2, out);
}